// round 16
// baseline (speedup 1.0000x reference)
#include <cuda_runtime.h>
#include <cuda_fp16.h>
#include <math.h>
#include <stdint.h>

#define NN 4096
#define DD 1024
#define HH 4096
#define NH2 2048   // row half

// ---------------- scratch (no allocations allowed) ----------------
__device__ __half g_qh[(size_t)NN * HH];
__device__ __half g_kh[(size_t)NN * HH];
__device__ __half g_vh[(size_t)NN * HH];
__device__ __half g_vTh[(size_t)HH * NN];
__device__ __half g_sh[(size_t)NN * NN];
__device__ float  g_s[(size_t)NN * NN];
__device__ float  g_t[(size_t)NN * DD];
__device__ float  g_h[(size_t)NN * DD];
__device__ __half g_hh[(size_t)NN * DD];
__device__ __half g_xh[(size_t)NN * DD];
__device__ __half g_avh[(size_t)NN * HH];
__device__ __half g_ff1h[(size_t)NN * HH];
__device__ __half g_WqTh[(size_t)HH * DD];
__device__ __half g_WkTh[(size_t)HH * DD];
__device__ __half g_WvTh[(size_t)HH * DD];
__device__ __half g_WoTh[(size_t)DD * HH];
__device__ __half g_W1Th[(size_t)HH * DD];
__device__ __half g_W2Th[(size_t)DD * HH];

__device__ __forceinline__ uint32_t smem_u32(const void* p) {
    uint32_t a;
    asm("{ .reg .u64 t; cvta.to.shared.u64 t, %1; cvt.u32.u64 %0, t; }"
        : "=r"(a) : "l"(p));
    return a;
}
__device__ __forceinline__ void ldsm_x4(uint32_t* r, uint32_t addr) {
    asm volatile("ldmatrix.sync.aligned.m8n8.x4.shared.b16 {%0,%1,%2,%3}, [%4];"
                 : "=r"(r[0]), "=r"(r[1]), "=r"(r[2]), "=r"(r[3]) : "r"(addr));
}
__device__ __forceinline__ void mma_f16(float* c, const uint32_t* a, uint32_t b0, uint32_t b1) {
    asm volatile(
        "mma.sync.aligned.m16n8k16.row.col.f32.f16.f16.f32 "
        "{%0,%1,%2,%3}, {%4,%5,%6,%7}, {%8,%9}, {%0,%1,%2,%3};"
        : "+f"(c[0]), "+f"(c[1]), "+f"(c[2]), "+f"(c[3])
        : "r"(a[0]), "r"(a[1]), "r"(a[2]), "r"(a[3]), "r"(b0), "r"(b1));
}
__device__ __forceinline__ uint32_t h2_as_u32(__half2 h) {
    return *reinterpret_cast<uint32_t*>(&h);
}

// ---------------- FP16 tensor-core GEMM (NT) — best-known config ------------
#define STAGE_B 32768
#define NSTAGE 3
#define GEMM_SMEM (NSTAGE * STAGE_B)

template<bool BIAS, bool RELU, bool OUTH>
__global__ __launch_bounds__(256, 2) void hgemm(const __half* __restrict__ A,
                                                const __half* __restrict__ B,
                                                const float* __restrict__ bias,
                                                void* __restrict__ Cv,
                                                int M, int N, int K) {
    extern __shared__ char smem[];
    const uint32_t sbase = smem_u32(smem);
    const int tid = threadIdx.x;
    const int lane = tid & 31;
    const int g = lane >> 2;
    const int t = lane & 3;
    const int warp = tid >> 5;
    const int wm = warp >> 1;
    const int wn = warp & 1;
    const int bm = blockIdx.y * 128;
    const int bn = blockIdx.x * 128;

    float acc[2][8][4];
#pragma unroll
    for (int mi = 0; mi < 2; mi++)
#pragma unroll
        for (int nj = 0; nj < 8; nj++)
#pragma unroll
            for (int e = 0; e < 4; e++) acc[mi][nj][e] = 0.0f;

    const int nch = K / 64;

    auto issueAB = [&](int c, int s) {
#pragma unroll
        for (int l = 0; l < 4; l++) {
            int f = tid + l * 256;
            int row = f >> 3;
            int seg = f & 7;
            uint32_t sw = (uint32_t)(row * 128 + ((seg ^ (row & 7)) << 4));
            uint32_t stage = sbase + (uint32_t)(s * STAGE_B);
            const __half* sa = A + (size_t)(bm + row) * K + c * 64 + seg * 8;
            const __half* sb = B + (size_t)(bn + row) * K + c * 64 + seg * 8;
            asm volatile("cp.async.cg.shared.global [%0], [%1], 16;"
                         :: "r"(stage + sw), "l"(sa) : "memory");
            asm volatile("cp.async.cg.shared.global [%0], [%1], 16;"
                         :: "r"(stage + 16384 + sw), "l"(sb) : "memory");
        }
        asm volatile("cp.async.commit_group;" ::: "memory");
    };

    const int lan7 = lane & 7;
    const int m_loc0 = wm * 32 + lan7 + ((lane >> 3) & 1) * 8;
    const int a_seghi = lane >> 4;
    const int n_base = wn * 64 + lan7 + ((lane >> 4) << 3);
    const int b_seghi = (lane >> 3) & 1;

    issueAB(0, 0);
    issueAB(1, 1);

    int s = 0;
    for (int c = 0; c < nch; c++) {
        if (c + 1 < nch) {
            asm volatile("cp.async.wait_group 1;" ::: "memory");
        } else {
            asm volatile("cp.async.wait_group 0;" ::: "memory");
        }
        __syncthreads();
        if (c + 2 < nch) {
            int s2 = s + 2;
            if (s2 >= NSTAGE) s2 -= NSTAGE;
            issueAB(c + 2, s2);
        }

        const uint32_t a_st = sbase + (uint32_t)(s * STAGE_B);
        const uint32_t b_st = a_st + 16384;

#pragma unroll
        for (int ks = 0; ks < 4; ks++) {
            uint32_t a[2][4];
#pragma unroll
            for (int mi = 0; mi < 2; mi++) {
                int m = m_loc0 + mi * 16;
                uint32_t addr = a_st + m * 128 +
                                (((2 * ks + a_seghi) ^ lan7) << 4);
                ldsm_x4(a[mi], addr);
            }
#pragma unroll
            for (int p = 0; p < 4; p++) {
                uint32_t bb[4];
                int n = n_base + p * 16;
                uint32_t addr = b_st + n * 128 +
                                (((2 * ks + b_seghi) ^ lan7) << 4);
                ldsm_x4(bb, addr);
                mma_f16(acc[0][2 * p], a[0], bb[0], bb[1]);
                mma_f16(acc[1][2 * p], a[1], bb[0], bb[1]);
                mma_f16(acc[0][2 * p + 1], a[0], bb[2], bb[3]);
                mma_f16(acc[1][2 * p + 1], a[1], bb[2], bb[3]);
            }
        }
        if (++s == NSTAGE) s = 0;
    }

    // ---- epilogue ----
#pragma unroll
    for (int mi = 0; mi < 2; mi++) {
        int r0 = bm + wm * 32 + mi * 16 + g;
        int r1 = r0 + 8;
#pragma unroll
        for (int nj = 0; nj < 8; nj++) {
            int col = bn + wn * 64 + nj * 8 + 2 * t;
            float v0 = acc[mi][nj][0], v1 = acc[mi][nj][1];
            float v2 = acc[mi][nj][2], v3 = acc[mi][nj][3];
            if (BIAS) {
                float bb0 = bias[col], bb1 = bias[col + 1];
                v0 += bb0; v1 += bb1; v2 += bb0; v3 += bb1;
            }
            if (RELU) {
                v0 = fmaxf(v0, 0.0f); v1 = fmaxf(v1, 0.0f);
                v2 = fmaxf(v2, 0.0f); v3 = fmaxf(v3, 0.0f);
            }
            if (OUTH) {
                __half2* C = (__half2*)Cv;
                C[((size_t)r0 * N + col) >> 1] = __floats2half2_rn(v0, v1);
                C[((size_t)r1 * N + col) >> 1] = __floats2half2_rn(v2, v3);
            } else {
                float* C = (float*)Cv;
                *(float2*)(C + (size_t)r0 * N + col) = make_float2(v0, v1);
                *(float2*)(C + (size_t)r1 * N + col) = make_float2(v2, v3);
            }
        }
    }
}

// ---------------- vectorized conversions / transposes ----------------------
__global__ __launch_bounds__(256) void f2h_vec(const float* __restrict__ in,
                                               __half* __restrict__ out, int n4) {
    int i = (blockIdx.x * 256 + threadIdx.x) * 4;
    if (i + 3 < n4) {
        const float4* in4 = (const float4*)in;
        uint2* out2 = (uint2*)out;
        float4 v[4];
#pragma unroll
        for (int j = 0; j < 4; j++) v[j] = in4[i + j];
#pragma unroll
        for (int j = 0; j < 4; j++) {
            uint2 u;
            u.x = h2_as_u32(__floats2half2_rn(v[j].x, v[j].y));
            u.y = h2_as_u32(__floats2half2_rn(v[j].z, v[j].w));
            out2[i + j] = u;
        }
    }
}

__global__ __launch_bounds__(256) void transpose_f2h(const float* __restrict__ in,
                                                     __half* __restrict__ out,
                                                     int rows, int cols) {
    __shared__ float tile[64][65];
    int c0 = blockIdx.x * 64;
    int r0 = blockIdx.y * 64;
    int tr = threadIdx.x >> 4;
    int tc4 = (threadIdx.x & 15) * 4;
#pragma unroll
    for (int i = 0; i < 4; i++) {
        int r = tr + i * 16;
        float4 v = *(const float4*)(in + (size_t)(r0 + r) * cols + c0 + tc4);
        tile[r][tc4 + 0] = v.x;
        tile[r][tc4 + 1] = v.y;
        tile[r][tc4 + 2] = v.z;
        tile[r][tc4 + 3] = v.w;
    }
    __syncthreads();
    int tcc = threadIdx.x >> 4;
    int tr4 = (threadIdx.x & 15) * 4;
#pragma unroll
    for (int i = 0; i < 4; i++) {
        int c = tcc + i * 16;
        uint2 u;
        u.x = h2_as_u32(__floats2half2_rn(tile[tr4 + 0][c], tile[tr4 + 1][c]));
        u.y = h2_as_u32(__floats2half2_rn(tile[tr4 + 2][c], tile[tr4 + 3][c]));
        *(uint2*)(out + (size_t)(c0 + c) * rows + r0 + tr4) = u;
    }
}

__global__ __launch_bounds__(256) void transpose_h2h(const __half* __restrict__ in,
                                                     __half* __restrict__ out,
                                                     int rows, int cols) {
    __shared__ __half tile[64][68];
    int c0 = blockIdx.x * 64;
    int r0 = blockIdx.y * 64;
    int tr = threadIdx.x >> 4;
    int tc4 = (threadIdx.x & 15) * 4;
#pragma unroll
    for (int i = 0; i < 4; i++) {
        int r = tr + i * 16;
        uint2 u = *(const uint2*)(in + (size_t)(r0 + r) * cols + c0 + tc4);
        *(uint2*)&tile[r][tc4] = u;
    }
    __syncthreads();
    int tcc = threadIdx.x >> 4;
    int tr4 = (threadIdx.x & 15) * 4;
#pragma unroll
    for (int i = 0; i < 4; i++) {
        int c = tcc + i * 16;
        __half2 h0 = __halves2half2(tile[tr4 + 0][c], tile[tr4 + 1][c]);
        __half2 h1 = __halves2half2(tile[tr4 + 2][c], tile[tr4 + 3][c]);
        uint2 u;
        u.x = h2_as_u32(h0);
        u.y = h2_as_u32(h1);
        *(uint2*)(out + (size_t)(c0 + c) * rows + r0 + tr4) = u;
    }
}

// ---------------- reductions ----------------
__device__ __forceinline__ float block_reduce_max(float v) {
    __shared__ float sh[32];
    int lane = threadIdx.x & 31, w = threadIdx.x >> 5;
#pragma unroll
    for (int o = 16; o > 0; o >>= 1) v = fmaxf(v, __shfl_xor_sync(0xffffffffu, v, o));
    if (lane == 0) sh[w] = v;
    __syncthreads();
    if (threadIdx.x < 32) {
        float t = (lane < (int)(blockDim.x >> 5)) ? sh[lane] : -INFINITY;
#pragma unroll
        for (int o = 16; o > 0; o >>= 1) t = fmaxf(t, __shfl_xor_sync(0xffffffffu, t, o));
        if (lane == 0) sh[0] = t;
    }
    __syncthreads();
    float r = sh[0];
    __syncthreads();
    return r;
}

__device__ __forceinline__ float2 block_reduce_sum2(float a, float b) {
    __shared__ float sha[32], shb[32];
    int lane = threadIdx.x & 31, w = threadIdx.x >> 5;
#pragma unroll
    for (int o = 16; o > 0; o >>= 1) {
        a += __shfl_xor_sync(0xffffffffu, a, o);
        b += __shfl_xor_sync(0xffffffffu, b, o);
    }
    if (lane == 0) { sha[w] = a; shb[w] = b; }
    __syncthreads();
    if (threadIdx.x < 32) {
        int nw = (int)(blockDim.x >> 5);
        float ta = (lane < nw) ? sha[lane] : 0.0f;
        float tb = (lane < nw) ? shb[lane] : 0.0f;
#pragma unroll
        for (int o = 16; o > 0; o >>= 1) {
            ta += __shfl_xor_sync(0xffffffffu, ta, o);
            tb += __shfl_xor_sync(0xffffffffu, tb, o);
        }
        if (lane == 0) { sha[0] = ta; shb[0] = tb; }
    }
    __syncthreads();
    float2 r = make_float2(sha[0], shb[0]);
    __syncthreads();
    return r;
}

// ---------------- softmax: f32 in (float4), half out (uint2) ---------------
__global__ __launch_bounds__(256) void softmax_rows(const float* __restrict__ S,
                                                    __half* __restrict__ Sh) {
    const int row = blockIdx.x;
    const float4* p4 = (const float4*)(S + (size_t)row * NN);
    uint2* ph2 = (uint2*)(Sh + (size_t)row * NN);
    const int tid = threadIdx.x;
    float4 v[4];
    float mx = -INFINITY;
#pragma unroll
    for (int i = 0; i < 4; i++) {
        v[i] = p4[tid + i * 256];
        mx = fmaxf(mx, fmaxf(fmaxf(v[i].x, v[i].y), fmaxf(v[i].z, v[i].w)));
    }
    mx = block_reduce_max(mx);
    float s = 0.0f;
#pragma unroll
    for (int i = 0; i < 4; i++) {
        v[i].x = __expf(v[i].x - mx);
        v[i].y = __expf(v[i].y - mx);
        v[i].z = __expf(v[i].z - mx);
        v[i].w = __expf(v[i].w - mx);
        s += (v[i].x + v[i].y) + (v[i].z + v[i].w);
    }
    float2 r = block_reduce_sum2(s, 0.0f);
    float inv = 1.0f / r.x;
#pragma unroll
    for (int i = 0; i < 4; i++) {
        uint2 u;
        u.x = h2_as_u32(__floats2half2_rn(v[i].x * inv, v[i].y * inv));
        u.y = h2_as_u32(__floats2half2_rn(v[i].z * inv, v[i].w * inv));
        ph2[tid + i * 256] = u;
    }
}

// ---------------- out = LayerNorm(x + res)*g + b (+ optional half copy) ----
__global__ __launch_bounds__(256) void add_layernorm(const float* __restrict__ x,
                                                     const float* __restrict__ res,
                                                     const float* __restrict__ gamma,
                                                     const float* __restrict__ beta,
                                                     float* __restrict__ out,
                                                     __half* __restrict__ outH) {
    const int row = blockIdx.x;
    const int tid = threadIdx.x;
    const int c4 = tid * 4;
    float4 a = *(const float4*)(x + (size_t)row * DD + c4);
    float4 b = *(const float4*)(res + (size_t)row * DD + c4);
    float4 v = make_float4(a.x + b.x, a.y + b.y, a.z + b.z, a.w + b.w);
    float s = (v.x + v.y) + (v.z + v.w);
    float s2 = (v.x * v.x + v.y * v.y) + (v.z * v.z + v.w * v.w);
    float2 r = block_reduce_sum2(s, s2);
    float mu = r.x * (1.0f / DD);
    float var = r.y * (1.0f / DD) - mu * mu;
    float rstd = rsqrtf(var + 1e-5f);
    float4 gm = *(const float4*)(gamma + c4);
    float4 bt = *(const float4*)(beta + c4);
    float4 o;
    o.x = (v.x - mu) * rstd * gm.x + bt.x;
    o.y = (v.y - mu) * rstd * gm.y + bt.y;
    o.z = (v.z - mu) * rstd * gm.z + bt.z;
    o.w = (v.w - mu) * rstd * gm.w + bt.w;
    *(float4*)(out + (size_t)row * DD + c4) = o;
    if (outH) {
        uint2 u;
        u.x = h2_as_u32(__floats2half2_rn(o.x, o.y));
        u.y = h2_as_u32(__floats2half2_rn(o.z, o.w));
        *(uint2*)(outH + (size_t)row * DD + c4) = u;
    }
}

// ---------------- launch ----------------
extern "C" void kernel_launch(void* const* d_in, const int* in_sizes, int n_in,
                              void* d_out, int out_size) {
    const float* x   = (const float*)d_in[0];
    const float* Wq  = (const float*)d_in[1];
    const float* Wk  = (const float*)d_in[2];
    const float* Wv  = (const float*)d_in[3];
    const float* Wo  = (const float*)d_in[4];
    const float* W1  = (const float*)d_in[5];
    const float* b1  = (const float*)d_in[6];
    const float* W2  = (const float*)d_in[7];
    const float* b2  = (const float*)d_in[8];
    const float* g1  = (const float*)d_in[9];
    const float* be1 = (const float*)d_in[10];
    const float* g2  = (const float*)d_in[11];
    const float* be2 = (const float*)d_in[12];
    float* out = (float*)d_out;

    __half *qh, *kh, *vh, *vTh, *sh, *hh, *xh, *avh, *ff1h;
    __half *WqTh, *WkTh, *WvTh, *WoTh, *W1Th, *W2Th;
    float *s, *t, *h;
    cudaGetSymbolAddress((void**)&qh, g_qh);
    cudaGetSymbolAddress((void**)&kh, g_kh);
    cudaGetSymbolAddress((void**)&vh, g_vh);
    cudaGetSymbolAddress((void**)&vTh, g_vTh);
    cudaGetSymbolAddress((void**)&sh, g_sh);
    cudaGetSymbolAddress((void**)&s, g_s);
    cudaGetSymbolAddress((void**)&t, g_t);
    cudaGetSymbolAddress((void**)&h, g_h);
    cudaGetSymbolAddress((void**)&hh, g_hh);
    cudaGetSymbolAddress((void**)&xh, g_xh);
    cudaGetSymbolAddress((void**)&avh, g_avh);
    cudaGetSymbolAddress((void**)&ff1h, g_ff1h);
    cudaGetSymbolAddress((void**)&WqTh, g_WqTh);
    cudaGetSymbolAddress((void**)&WkTh, g_WkTh);
    cudaGetSymbolAddress((void**)&WvTh, g_WvTh);
    cudaGetSymbolAddress((void**)&WoTh, g_WoTh);
    cudaGetSymbolAddress((void**)&W1Th, g_W1Th);
    cudaGetSymbolAddress((void**)&W2Th, g_W2Th);

    cudaFuncSetAttribute(hgemm<false, false, true>,
                         cudaFuncAttributeMaxDynamicSharedMemorySize, GEMM_SMEM);
    cudaFuncSetAttribute(hgemm<false, false, false>,
                         cudaFuncAttributeMaxDynamicSharedMemorySize, GEMM_SMEM);
    cudaFuncSetAttribute(hgemm<true, true, true>,
                         cudaFuncAttributeMaxDynamicSharedMemorySize, GEMM_SMEM);
    cudaFuncSetAttribute(hgemm<true, false, false>,
                         cudaFuncAttributeMaxDynamicSharedMemorySize, GEMM_SMEM);

    // lazy one-time side stream + events (host-side resources, no device mem)
    static cudaStream_t s2 = nullptr;
    static cudaEvent_t ev_fork, ev_qkvw, ev_late, ev_v, ev_vT;
    static cudaEvent_t e_s0, e_s1, e_sm0, e_sm1, e_av0, e_at0;
    if (!s2) {
        cudaStreamCreateWithFlags(&s2, cudaStreamNonBlocking);
        cudaEventCreateWithFlags(&ev_fork, cudaEventDisableTiming);
        cudaEventCreateWithFlags(&ev_qkvw, cudaEventDisableTiming);
        cudaEventCreateWithFlags(&ev_late, cudaEventDisableTiming);
        cudaEventCreateWithFlags(&ev_v, cudaEventDisableTiming);
        cudaEventCreateWithFlags(&ev_vT, cudaEventDisableTiming);
        cudaEventCreateWithFlags(&e_s0, cudaEventDisableTiming);
        cudaEventCreateWithFlags(&e_s1, cudaEventDisableTiming);
        cudaEventCreateWithFlags(&e_sm0, cudaEventDisableTiming);
        cudaEventCreateWithFlags(&e_sm1, cudaEventDisableTiming);
        cudaEventCreateWithFlags(&e_av0, cudaEventDisableTiming);
        cudaEventCreateWithFlags(&e_at0, cudaEventDisableTiming);
    }

    dim3 blk(256);
    dim3 grid_NH(HH / 128, NN / 128);        // 32 x 32
    dim3 grid_NH_half(HH / 128, NH2 / 128);  // 32 x 16
    dim3 grid_ND(DD / 128, NN / 128);        // 8 x 32
    dim3 grid_ND_half(DD / 128, NH2 / 128);  // 8 x 16
    dim3 tgrid_DH(HH / 64, DD / 64);
    dim3 tgrid_HD(DD / 64, HH / 64);
    dim3 tgrid_NHh(HH / 64, NN / 64);

    // row-half pointer offsets
    __half* qh1  = qh + (size_t)NH2 * HH;
    float*  s1p  = s + (size_t)NH2 * NN;
    __half* sh1  = sh + (size_t)NH2 * NN;
    __half* avh1 = avh + (size_t)NH2 * HH;
    float*  t1p  = t + (size_t)NH2 * DD;

    // ---- fork side stream ----
    cudaEventRecord(ev_fork, 0);
    cudaStreamWaitEvent(s2, ev_fork, 0);

    // side stream: Wk/Wv transposes, then late weights
    transpose_f2h<<<tgrid_DH, blk, 0, s2>>>(Wk, WkTh, DD, HH);
    transpose_f2h<<<tgrid_DH, blk, 0, s2>>>(Wv, WvTh, DD, HH);
    cudaEventRecord(ev_qkvw, s2);
    transpose_f2h<<<tgrid_HD, blk, 0, s2>>>(Wo, WoTh, HH, DD);
    transpose_f2h<<<tgrid_DH, blk, 0, s2>>>(W1, W1Th, DD, HH);
    transpose_f2h<<<tgrid_HD, blk, 0, s2>>>(W2, W2Th, HH, DD);
    cudaEventRecord(ev_late, s2);

    // main stream: x->half, Wq transpose
    f2h_vec<<<(NN * DD / 16 + 255) / 256, blk>>>(x, xh, NN * DD / 4);
    transpose_f2h<<<tgrid_DH, blk>>>(Wq, WqTh, DD, HH);
    cudaStreamWaitEvent(0, ev_qkvw, 0);

    // projections
    hgemm<false, false, true><<<grid_NH, blk, GEMM_SMEM>>>(xh, WqTh, nullptr, qh, NN, HH, DD);
    hgemm<false, false, true><<<grid_NH, blk, GEMM_SMEM>>>(xh, WkTh, nullptr, kh, NN, HH, DD);
    hgemm<false, false, true><<<grid_NH, blk, GEMM_SMEM>>>(xh, WvTh, nullptr, vh, NN, HH, DD);
    cudaEventRecord(ev_v, 0);

    // side stream: vT transpose overlaps scores on main
    cudaStreamWaitEvent(s2, ev_v, 0);
    transpose_h2h<<<tgrid_NHh, blk, 0, s2>>>(vh, vTh, NN, HH);
    cudaEventRecord(ev_vT, s2);

    // ---- attention pipeline in row-halves ----
    // scores half 0 (rows 0..2047)
    hgemm<false, false, false><<<grid_NH_half, blk, GEMM_SMEM>>>(
        qh, kh, nullptr, s, NH2, NN, HH);
    cudaEventRecord(e_s0, 0);
    // scores half 1 (rows 2048..4095)
    hgemm<false, false, false><<<grid_NH_half, blk, GEMM_SMEM>>>(
        qh1, kh, nullptr, s1p, NH2, NN, HH);
    cudaEventRecord(e_s1, 0);

    // side: softmax halves (overlap with main GEMMs)
    cudaStreamWaitEvent(s2, e_s0, 0);
    softmax_rows<<<NH2, blk, 0, s2>>>(s, sh);
    cudaEventRecord(e_sm0, s2);
    cudaStreamWaitEvent(s2, e_s1, 0);
    softmax_rows<<<NH2, blk, 0, s2>>>(s1p, sh1);
    cudaEventRecord(e_sm1, s2);

    // main: av half 0 (needs sm0 + vT)
    cudaStreamWaitEvent(0, e_sm0, 0);
    cudaStreamWaitEvent(0, ev_vT, 0);
    hgemm<false, false, true><<<grid_NH_half, blk, GEMM_SMEM>>>(
        sh, vTh, nullptr, avh, NH2, HH, NN);
    cudaEventRecord(e_av0, 0);

    // side: attn half 0 (needs av0 + WoT) — overlaps av half 1 on main
    cudaStreamWaitEvent(s2, e_av0, 0);
    cudaStreamWaitEvent(s2, ev_late, 0);
    hgemm<false, false, false><<<grid_ND_half, blk, 0 + GEMM_SMEM, s2>>>(
        avh, WoTh, nullptr, t, NH2, DD, HH);
    cudaEventRecord(e_at0, s2);

    // main: av half 1
    cudaStreamWaitEvent(0, e_sm1, 0);
    hgemm<false, false, true><<<grid_NH_half, blk, GEMM_SMEM>>>(
        sh1, vTh, nullptr, avh1, NH2, HH, NN);

    // main: attn half 1 (needs WoT; av1 in-stream)
    cudaStreamWaitEvent(0, ev_late, 0);
    hgemm<false, false, false><<<grid_ND_half, blk, GEMM_SMEM>>>(
        avh1, WoTh, nullptr, t1p, NH2, DD, HH);

    // join: LN1 needs both attn halves
    cudaStreamWaitEvent(0, e_at0, 0);
    add_layernorm<<<NN, blk>>>(x, t, g1, be1, h, hh);

    // ff1 = relu(h @ W1 + b1) -> half
    hgemm<true, true, true><<<grid_NH, blk, GEMM_SMEM>>>(hh, W1Th, b1, ff1h, NN, HH, DD);

    // ff2 = ff1 @ W2 + b2 (f32: residual)
    hgemm<true, false, false><<<grid_ND, blk, GEMM_SMEM>>>(ff1h, W2Th, b2, t, NN, DD, HH);

    // out = LN(h + ff2)
    add_layernorm<<<NN, blk>>>(h, t, g2, be2, out, nullptr);
}

// round 17
// speedup vs baseline: 1.0895x; 1.0895x over previous
#include <cuda_runtime.h>
#include <cuda_fp16.h>
#include <math.h>
#include <stdint.h>

#define NN 4096
#define DD 1024
#define HH 4096

// ---------------- scratch (no allocations allowed) ----------------
__device__ __half g_qh[(size_t)NN * HH];
__device__ __half g_kh[(size_t)NN * HH];
__device__ __half g_vh[(size_t)NN * HH];
__device__ __half g_vTh[(size_t)HH * NN];
__device__ __half g_sh[(size_t)NN * NN];
__device__ float  g_s[(size_t)NN * NN];
__device__ float  g_t[(size_t)NN * DD];
__device__ float  g_h[(size_t)NN * DD];
__device__ __half g_hh[(size_t)NN * DD];
__device__ __half g_xh[(size_t)NN * DD];
__device__ __half g_avh[(size_t)NN * HH];
__device__ __half g_ff1h[(size_t)NN * HH];
__device__ __half g_WqTh[(size_t)HH * DD];
__device__ __half g_WkTh[(size_t)HH * DD];
__device__ __half g_WvTh[(size_t)HH * DD];
__device__ __half g_WoTh[(size_t)DD * HH];
__device__ __half g_W1Th[(size_t)HH * DD];
__device__ __half g_W2Th[(size_t)DD * HH];

__device__ __forceinline__ uint32_t smem_u32(const void* p) {
    uint32_t a;
    asm("{ .reg .u64 t; cvta.to.shared.u64 t, %1; cvt.u32.u64 %0, t; }"
        : "=r"(a) : "l"(p));
    return a;
}
__device__ __forceinline__ void ldsm_x4(uint32_t* r, uint32_t addr) {
    asm volatile("ldmatrix.sync.aligned.m8n8.x4.shared.b16 {%0,%1,%2,%3}, [%4];"
                 : "=r"(r[0]), "=r"(r[1]), "=r"(r[2]), "=r"(r[3]) : "r"(addr));
}
__device__ __forceinline__ void mma_f16(float* c, const uint32_t* a, uint32_t b0, uint32_t b1) {
    asm volatile(
        "mma.sync.aligned.m16n8k16.row.col.f32.f16.f16.f32 "
        "{%0,%1,%2,%3}, {%4,%5,%6,%7}, {%8,%9}, {%0,%1,%2,%3};"
        : "+f"(c[0]), "+f"(c[1]), "+f"(c[2]), "+f"(c[3])
        : "r"(a[0]), "r"(a[1]), "r"(a[2]), "r"(a[3]), "r"(b0), "r"(b1));
}
__device__ __forceinline__ uint32_t h2_as_u32(__half2 h) {
    return *reinterpret_cast<uint32_t*>(&h);
}

// ---------------- FP16 tensor-core GEMM (NT) — best-known config ------------
#define STAGE_B 32768
#define NSTAGE 3
#define GEMM_SMEM (NSTAGE * STAGE_B)

template<bool BIAS, bool RELU, bool OUTH>
__global__ __launch_bounds__(256, 2) void hgemm(const __half* __restrict__ A,
                                                const __half* __restrict__ B,
                                                const float* __restrict__ bias,
                                                void* __restrict__ Cv,
                                                int M, int N, int K) {
    extern __shared__ char smem[];
    const uint32_t sbase = smem_u32(smem);
    const int tid = threadIdx.x;
    const int lane = tid & 31;
    const int g = lane >> 2;
    const int t = lane & 3;
    const int warp = tid >> 5;
    const int wm = warp >> 1;
    const int wn = warp & 1;
    const int bm = blockIdx.y * 128;
    const int bn = blockIdx.x * 128;

    float acc[2][8][4];
#pragma unroll
    for (int mi = 0; mi < 2; mi++)
#pragma unroll
        for (int nj = 0; nj < 8; nj++)
#pragma unroll
            for (int e = 0; e < 4; e++) acc[mi][nj][e] = 0.0f;

    const int nch = K / 64;

    auto issueAB = [&](int c, int s) {
#pragma unroll
        for (int l = 0; l < 4; l++) {
            int f = tid + l * 256;
            int row = f >> 3;
            int seg = f & 7;
            uint32_t sw = (uint32_t)(row * 128 + ((seg ^ (row & 7)) << 4));
            uint32_t stage = sbase + (uint32_t)(s * STAGE_B);
            const __half* sa = A + (size_t)(bm + row) * K + c * 64 + seg * 8;
            const __half* sb = B + (size_t)(bn + row) * K + c * 64 + seg * 8;
            asm volatile("cp.async.cg.shared.global [%0], [%1], 16;"
                         :: "r"(stage + sw), "l"(sa) : "memory");
            asm volatile("cp.async.cg.shared.global [%0], [%1], 16;"
                         :: "r"(stage + 16384 + sw), "l"(sb) : "memory");
        }
        asm volatile("cp.async.commit_group;" ::: "memory");
    };

    const int lan7 = lane & 7;
    const int m_loc0 = wm * 32 + lan7 + ((lane >> 3) & 1) * 8;
    const int a_seghi = lane >> 4;
    const int n_base = wn * 64 + lan7 + ((lane >> 4) << 3);
    const int b_seghi = (lane >> 3) & 1;

    issueAB(0, 0);
    issueAB(1, 1);

    int s = 0;
    for (int c = 0; c < nch; c++) {
        if (c + 1 < nch) {
            asm volatile("cp.async.wait_group 1;" ::: "memory");
        } else {
            asm volatile("cp.async.wait_group 0;" ::: "memory");
        }
        __syncthreads();
        if (c + 2 < nch) {
            int s2 = s + 2;
            if (s2 >= NSTAGE) s2 -= NSTAGE;
            issueAB(c + 2, s2);
        }

        const uint32_t a_st = sbase + (uint32_t)(s * STAGE_B);
        const uint32_t b_st = a_st + 16384;

#pragma unroll
        for (int ks = 0; ks < 4; ks++) {
            uint32_t a[2][4];
#pragma unroll
            for (int mi = 0; mi < 2; mi++) {
                int m = m_loc0 + mi * 16;
                uint32_t addr = a_st + m * 128 +
                                (((2 * ks + a_seghi) ^ lan7) << 4);
                ldsm_x4(a[mi], addr);
            }
#pragma unroll
            for (int p = 0; p < 4; p++) {
                uint32_t bb[4];
                int n = n_base + p * 16;
                uint32_t addr = b_st + n * 128 +
                                (((2 * ks + b_seghi) ^ lan7) << 4);
                ldsm_x4(bb, addr);
                mma_f16(acc[0][2 * p], a[0], bb[0], bb[1]);
                mma_f16(acc[1][2 * p], a[1], bb[0], bb[1]);
                mma_f16(acc[0][2 * p + 1], a[0], bb[2], bb[3]);
                mma_f16(acc[1][2 * p + 1], a[1], bb[2], bb[3]);
            }
        }
        if (++s == NSTAGE) s = 0;
    }

    // ---- epilogue ----
#pragma unroll
    for (int mi = 0; mi < 2; mi++) {
        int r0 = bm + wm * 32 + mi * 16 + g;
        int r1 = r0 + 8;
#pragma unroll
        for (int nj = 0; nj < 8; nj++) {
            int col = bn + wn * 64 + nj * 8 + 2 * t;
            float v0 = acc[mi][nj][0], v1 = acc[mi][nj][1];
            float v2 = acc[mi][nj][2], v3 = acc[mi][nj][3];
            if (BIAS) {
                float bb0 = bias[col], bb1 = bias[col + 1];
                v0 += bb0; v1 += bb1; v2 += bb0; v3 += bb1;
            }
            if (RELU) {
                v0 = fmaxf(v0, 0.0f); v1 = fmaxf(v1, 0.0f);
                v2 = fmaxf(v2, 0.0f); v3 = fmaxf(v3, 0.0f);
            }
            if (OUTH) {
                __half2* C = (__half2*)Cv;
                C[((size_t)r0 * N + col) >> 1] = __floats2half2_rn(v0, v1);
                C[((size_t)r1 * N + col) >> 1] = __floats2half2_rn(v2, v3);
            } else {
                float* C = (float*)Cv;
                *(float2*)(C + (size_t)r0 * N + col) = make_float2(v0, v1);
                *(float2*)(C + (size_t)r1 * N + col) = make_float2(v2, v3);
            }
        }
    }
}

// ---------------- vectorized conversions / transposes ----------------------
__global__ __launch_bounds__(256) void f2h_vec(const float* __restrict__ in,
                                               __half* __restrict__ out, int n4) {
    int i = (blockIdx.x * 256 + threadIdx.x) * 4;
    if (i + 3 < n4) {
        const float4* in4 = (const float4*)in;
        uint2* out2 = (uint2*)out;
        float4 v[4];
#pragma unroll
        for (int j = 0; j < 4; j++) v[j] = in4[i + j];
#pragma unroll
        for (int j = 0; j < 4; j++) {
            uint2 u;
            u.x = h2_as_u32(__floats2half2_rn(v[j].x, v[j].y));
            u.y = h2_as_u32(__floats2half2_rn(v[j].z, v[j].w));
            out2[i + j] = u;
        }
    }
}

__global__ __launch_bounds__(256) void transpose_f2h(const float* __restrict__ in,
                                                     __half* __restrict__ out,
                                                     int rows, int cols) {
    __shared__ float tile[64][65];
    int c0 = blockIdx.x * 64;
    int r0 = blockIdx.y * 64;
    int tr = threadIdx.x >> 4;
    int tc4 = (threadIdx.x & 15) * 4;
#pragma unroll
    for (int i = 0; i < 4; i++) {
        int r = tr + i * 16;
        float4 v = *(const float4*)(in + (size_t)(r0 + r) * cols + c0 + tc4);
        tile[r][tc4 + 0] = v.x;
        tile[r][tc4 + 1] = v.y;
        tile[r][tc4 + 2] = v.z;
        tile[r][tc4 + 3] = v.w;
    }
    __syncthreads();
    int tcc = threadIdx.x >> 4;
    int tr4 = (threadIdx.x & 15) * 4;
#pragma unroll
    for (int i = 0; i < 4; i++) {
        int c = tcc + i * 16;
        uint2 u;
        u.x = h2_as_u32(__floats2half2_rn(tile[tr4 + 0][c], tile[tr4 + 1][c]));
        u.y = h2_as_u32(__floats2half2_rn(tile[tr4 + 2][c], tile[tr4 + 3][c]));
        *(uint2*)(out + (size_t)(c0 + c) * rows + r0 + tr4) = u;
    }
}

__global__ __launch_bounds__(256) void transpose_h2h(const __half* __restrict__ in,
                                                     __half* __restrict__ out,
                                                     int rows, int cols) {
    __shared__ __half tile[64][68];
    int c0 = blockIdx.x * 64;
    int r0 = blockIdx.y * 64;
    int tr = threadIdx.x >> 4;
    int tc4 = (threadIdx.x & 15) * 4;
#pragma unroll
    for (int i = 0; i < 4; i++) {
        int r = tr + i * 16;
        uint2 u = *(const uint2*)(in + (size_t)(r0 + r) * cols + c0 + tc4);
        *(uint2*)&tile[r][tc4] = u;
    }
    __syncthreads();
    int tcc = threadIdx.x >> 4;
    int tr4 = (threadIdx.x & 15) * 4;
#pragma unroll
    for (int i = 0; i < 4; i++) {
        int c = tcc + i * 16;
        __half2 h0 = __halves2half2(tile[tr4 + 0][c], tile[tr4 + 1][c]);
        __half2 h1 = __halves2half2(tile[tr4 + 2][c], tile[tr4 + 3][c]);
        uint2 u;
        u.x = h2_as_u32(h0);
        u.y = h2_as_u32(h1);
        *(uint2*)(out + (size_t)(c0 + c) * rows + r0 + tr4) = u;
    }
}

// ---------------- reductions ----------------
__device__ __forceinline__ float block_reduce_max(float v) {
    __shared__ float sh[32];
    int lane = threadIdx.x & 31, w = threadIdx.x >> 5;
#pragma unroll
    for (int o = 16; o > 0; o >>= 1) v = fmaxf(v, __shfl_xor_sync(0xffffffffu, v, o));
    if (lane == 0) sh[w] = v;
    __syncthreads();
    if (threadIdx.x < 32) {
        float t = (lane < (int)(blockDim.x >> 5)) ? sh[lane] : -INFINITY;
#pragma unroll
        for (int o = 16; o > 0; o >>= 1) t = fmaxf(t, __shfl_xor_sync(0xffffffffu, t, o));
        if (lane == 0) sh[0] = t;
    }
    __syncthreads();
    float r = sh[0];
    __syncthreads();
    return r;
}

__device__ __forceinline__ float2 block_reduce_sum2(float a, float b) {
    __shared__ float sha[32], shb[32];
    int lane = threadIdx.x & 31, w = threadIdx.x >> 5;
#pragma unroll
    for (int o = 16; o > 0; o >>= 1) {
        a += __shfl_xor_sync(0xffffffffu, a, o);
        b += __shfl_xor_sync(0xffffffffu, b, o);
    }
    if (lane == 0) { sha[w] = a; shb[w] = b; }
    __syncthreads();
    if (threadIdx.x < 32) {
        int nw = (int)(blockDim.x >> 5);
        float ta = (lane < nw) ? sha[lane] : 0.0f;
        float tb = (lane < nw) ? shb[lane] : 0.0f;
#pragma unroll
        for (int o = 16; o > 0; o >>= 1) {
            ta += __shfl_xor_sync(0xffffffffu, ta, o);
            tb += __shfl_xor_sync(0xffffffffu, tb, o);
        }
        if (lane == 0) { sha[0] = ta; shb[0] = tb; }
    }
    __syncthreads();
    float2 r = make_float2(sha[0], shb[0]);
    __syncthreads();
    return r;
}

// ---------------- softmax: f32 in (float4), half out (uint2) ---------------
__global__ __launch_bounds__(256) void softmax_rows(const float* __restrict__ S,
                                                    __half* __restrict__ Sh) {
    const int row = blockIdx.x;
    const float4* p4 = (const float4*)(S + (size_t)row * NN);
    uint2* ph2 = (uint2*)(Sh + (size_t)row * NN);
    const int tid = threadIdx.x;
    float4 v[4];
    float mx = -INFINITY;
#pragma unroll
    for (int i = 0; i < 4; i++) {
        v[i] = p4[tid + i * 256];
        mx = fmaxf(mx, fmaxf(fmaxf(v[i].x, v[i].y), fmaxf(v[i].z, v[i].w)));
    }
    mx = block_reduce_max(mx);
    float s = 0.0f;
#pragma unroll
    for (int i = 0; i < 4; i++) {
        v[i].x = __expf(v[i].x - mx);
        v[i].y = __expf(v[i].y - mx);
        v[i].z = __expf(v[i].z - mx);
        v[i].w = __expf(v[i].w - mx);
        s += (v[i].x + v[i].y) + (v[i].z + v[i].w);
    }
    float2 r = block_reduce_sum2(s, 0.0f);
    float inv = 1.0f / r.x;
#pragma unroll
    for (int i = 0; i < 4; i++) {
        uint2 u;
        u.x = h2_as_u32(__floats2half2_rn(v[i].x * inv, v[i].y * inv));
        u.y = h2_as_u32(__floats2half2_rn(v[i].z * inv, v[i].w * inv));
        ph2[tid + i * 256] = u;
    }
}

// ---------------- out = LayerNorm(x + res)*g + b (+ optional half copy) ----
__global__ __launch_bounds__(256) void add_layernorm(const float* __restrict__ x,
                                                     const float* __restrict__ res,
                                                     const float* __restrict__ gamma,
                                                     const float* __restrict__ beta,
                                                     float* __restrict__ out,
                                                     __half* __restrict__ outH) {
    const int row = blockIdx.x;
    const int tid = threadIdx.x;
    const int c4 = tid * 4;
    float4 a = *(const float4*)(x + (size_t)row * DD + c4);
    float4 b = *(const float4*)(res + (size_t)row * DD + c4);
    float4 v = make_float4(a.x + b.x, a.y + b.y, a.z + b.z, a.w + b.w);
    float s = (v.x + v.y) + (v.z + v.w);
    float s2 = (v.x * v.x + v.y * v.y) + (v.z * v.z + v.w * v.w);
    float2 r = block_reduce_sum2(s, s2);
    float mu = r.x * (1.0f / DD);
    float var = r.y * (1.0f / DD) - mu * mu;
    float rstd = rsqrtf(var + 1e-5f);
    float4 gm = *(const float4*)(gamma + c4);
    float4 bt = *(const float4*)(beta + c4);
    float4 o;
    o.x = (v.x - mu) * rstd * gm.x + bt.x;
    o.y = (v.y - mu) * rstd * gm.y + bt.y;
    o.z = (v.z - mu) * rstd * gm.z + bt.z;
    o.w = (v.w - mu) * rstd * gm.w + bt.w;
    *(float4*)(out + (size_t)row * DD + c4) = o;
    if (outH) {
        uint2 u;
        u.x = h2_as_u32(__floats2half2_rn(o.x, o.y));
        u.y = h2_as_u32(__floats2half2_rn(o.z, o.w));
        *(uint2*)(outH + (size_t)row * DD + c4) = u;
    }
}

// ---------------- launch ----------------
extern "C" void kernel_launch(void* const* d_in, const int* in_sizes, int n_in,
                              void* d_out, int out_size) {
    const float* x   = (const float*)d_in[0];
    const float* Wq  = (const float*)d_in[1];
    const float* Wk  = (const float*)d_in[2];
    const float* Wv  = (const float*)d_in[3];
    const float* Wo  = (const float*)d_in[4];
    const float* W1  = (const float*)d_in[5];
    const float* b1  = (const float*)d_in[6];
    const float* W2  = (const float*)d_in[7];
    const float* b2  = (const float*)d_in[8];
    const float* g1  = (const float*)d_in[9];
    const float* be1 = (const float*)d_in[10];
    const float* g2  = (const float*)d_in[11];
    const float* be2 = (const float*)d_in[12];
    float* out = (float*)d_out;

    __half *qh, *kh, *vh, *vTh, *sh, *hh, *xh, *avh, *ff1h;
    __half *WqTh, *WkTh, *WvTh, *WoTh, *W1Th, *W2Th;
    float *s, *t, *h;
    cudaGetSymbolAddress((void**)&qh, g_qh);
    cudaGetSymbolAddress((void**)&kh, g_kh);
    cudaGetSymbolAddress((void**)&vh, g_vh);
    cudaGetSymbolAddress((void**)&vTh, g_vTh);
    cudaGetSymbolAddress((void**)&sh, g_sh);
    cudaGetSymbolAddress((void**)&s, g_s);
    cudaGetSymbolAddress((void**)&t, g_t);
    cudaGetSymbolAddress((void**)&h, g_h);
    cudaGetSymbolAddress((void**)&hh, g_hh);
    cudaGetSymbolAddress((void**)&xh, g_xh);
    cudaGetSymbolAddress((void**)&avh, g_avh);
    cudaGetSymbolAddress((void**)&ff1h, g_ff1h);
    cudaGetSymbolAddress((void**)&WqTh, g_WqTh);
    cudaGetSymbolAddress((void**)&WkTh, g_WkTh);
    cudaGetSymbolAddress((void**)&WvTh, g_WvTh);
    cudaGetSymbolAddress((void**)&WoTh, g_WoTh);
    cudaGetSymbolAddress((void**)&W1Th, g_W1Th);
    cudaGetSymbolAddress((void**)&W2Th, g_W2Th);

    cudaFuncSetAttribute(hgemm<false, false, true>,
                         cudaFuncAttributeMaxDynamicSharedMemorySize, GEMM_SMEM);
    cudaFuncSetAttribute(hgemm<false, false, false>,
                         cudaFuncAttributeMaxDynamicSharedMemorySize, GEMM_SMEM);
    cudaFuncSetAttribute(hgemm<true, true, true>,
                         cudaFuncAttributeMaxDynamicSharedMemorySize, GEMM_SMEM);
    cudaFuncSetAttribute(hgemm<true, false, false>,
                         cudaFuncAttributeMaxDynamicSharedMemorySize, GEMM_SMEM);

    // lazy one-time side stream + events (host-side resources, no device mem)
    static cudaStream_t s2 = nullptr;
    static cudaEvent_t ev_fork, ev_x, ev_k, ev_vT, ev_late;
    if (!s2) {
        cudaStreamCreateWithFlags(&s2, cudaStreamNonBlocking);
        cudaEventCreateWithFlags(&ev_fork, cudaEventDisableTiming);
        cudaEventCreateWithFlags(&ev_x, cudaEventDisableTiming);
        cudaEventCreateWithFlags(&ev_k, cudaEventDisableTiming);
        cudaEventCreateWithFlags(&ev_vT, cudaEventDisableTiming);
        cudaEventCreateWithFlags(&ev_late, cudaEventDisableTiming);
    }

    dim3 blk(256);
    dim3 grid_NH(HH / 128, NN / 128);    // 32 x 32
    dim3 grid_ND(DD / 128, NN / 128);    // 8 x 32
    dim3 tgrid_DH(HH / 64, DD / 64);
    dim3 tgrid_HD(DD / 64, HH / 64);
    dim3 tgrid_NHh(HH / 64, NN / 64);

    // ---- fork side stream ----
    cudaEventRecord(ev_fork, 0);
    cudaStreamWaitEvent(s2, ev_fork, 0);

    // main: x -> half, Wq transpose
    f2h_vec<<<(NN * DD / 16 + 255) / 256, blk>>>(x, xh, NN * DD / 4);
    cudaEventRecord(ev_x, 0);
    transpose_f2h<<<tgrid_DH, blk>>>(Wq, WqTh, DD, HH);

    // side: Wk/Wv transposes, then k-proj and v-proj (full-size launches)
    transpose_f2h<<<tgrid_DH, blk, 0, s2>>>(Wk, WkTh, DD, HH);
    transpose_f2h<<<tgrid_DH, blk, 0, s2>>>(Wv, WvTh, DD, HH);
    cudaStreamWaitEvent(s2, ev_x, 0);
    hgemm<false, false, true><<<grid_NH, blk, GEMM_SMEM, s2>>>(
        xh, WkTh, nullptr, kh, NN, HH, DD);
    cudaEventRecord(ev_k, s2);
    hgemm<false, false, true><<<grid_NH, blk, GEMM_SMEM, s2>>>(
        xh, WvTh, nullptr, vh, NN, HH, DD);
    transpose_h2h<<<tgrid_NHh, blk, 0, s2>>>(vh, vTh, NN, HH);
    cudaEventRecord(ev_vT, s2);
    transpose_f2h<<<tgrid_HD, blk, 0, s2>>>(Wo, WoTh, HH, DD);
    transpose_f2h<<<tgrid_DH, blk, 0, s2>>>(W1, W1Th, DD, HH);
    transpose_f2h<<<tgrid_HD, blk, 0, s2>>>(W2, W2Th, HH, DD);
    cudaEventRecord(ev_late, s2);

    // main: q-proj (overlaps k/v-proj on side)
    hgemm<false, false, true><<<grid_NH, blk, GEMM_SMEM>>>(
        xh, WqTh, nullptr, qh, NN, HH, DD);

    // scores = q @ k^T (needs k from side), softmax -> half
    cudaStreamWaitEvent(0, ev_k, 0);
    hgemm<false, false, false><<<grid_NH, blk, GEMM_SMEM>>>(
        qh, kh, nullptr, s, NN, NN, HH);
    softmax_rows<<<NN, blk>>>(s, sh);

    // av = softmax @ v (needs vT from side)
    cudaStreamWaitEvent(0, ev_vT, 0);
    hgemm<false, false, true><<<grid_NH, blk, GEMM_SMEM>>>(
        sh, vTh, nullptr, avh, NN, HH, NN);

    // attn = av @ Wo (needs late weights)
    cudaStreamWaitEvent(0, ev_late, 0);
    hgemm<false, false, false><<<grid_ND, blk, GEMM_SMEM>>>(
        avh, WoTh, nullptr, t, NN, DD, HH);

    // h = LN(x + attn) (+ half copy)
    add_layernorm<<<NN, blk>>>(x, t, g1, be1, h, hh);

    // ff1 = relu(h @ W1 + b1) -> half
    hgemm<true, true, true><<<grid_NH, blk, GEMM_SMEM>>>(hh, W1Th, b1, ff1h, NN, HH, DD);

    // ff2 = ff1 @ W2 + b2 (f32: residual)
    hgemm<true, false, false><<<grid_ND, blk, GEMM_SMEM>>>(ff1h, W2Th, b2, t, NN, DD, HH);

    // out = LN(h + ff2)
    add_layernorm<<<NN, blk>>>(h, t, g2, be2, out, nullptr);
}